// round 10
// baseline (speedup 1.0000x reference)
#include <cuda_runtime.h>
#include <cuda.h>
#include <cuda_fp16.h>
#include <cstdint>
#include <math.h>

// SphericalFilter via mma.sync.m16n8k16 fp16 (fp32 accumulate).
// out[p,h] = sum_k Y[p,k] * W[h,k] + b[h];  P=131072, H=1024, K=129 (pad 144)
//
// R10 = R9 with self-declared cuTensorMapEncodeTiled fn-pointer type (the
// toolkit's cudaTypedefs.h doesn't expose PFN_cuTensorMapEncodeTiled here).
// (a) epilogue via smem stage + TMA 2D tensor store (bulk_group) -- removes
// per-thread STG.128 issue cost; (b) grid 2048 (CTA = 128 p x 512 h) to cut
// wave-quantization tail. B staged by CTA-level cp.async.bulk ring.

#define NK 129
#define NKPAD 144
#define NKC 9               // k-chunks of 16
#define H_TOT 1024
#define TILE_P 128
#define NTHREADS 256
#define NHT 4               // h-tiles (128h) per CTA -> 512 h
#define NBLOCKS (NHT * NKC) // 36 4KB B-blocks per CTA
#define STAGES 8
#define PROD_AHEAD 4

#define AFRAG_HALFS (8 * NKC * 32 * 8)          // 36864 B
#define RING_OFF (AFRAG_HALFS * 2)              // 36864
#define RING_BYTES (STAGES * 4096)              // 32768
#define STAGE_OFF (RING_OFF + RING_BYTES)       // 69632: two 16KB out stages
#define MBAR_OFF (STAGE_OFF + 32768)            // 102400
#define SMEM_BYTES (MBAR_OFF + 128)             // 102528

// Self-declared driver API fn-pointer type (header lacks PFN_ typedef).
typedef CUresult (*tmap_encode_fn)(
    CUtensorMap*, CUtensorMapDataType, cuuint32_t, void*,
    const cuuint64_t*, const cuuint64_t*, const cuuint32_t*, const cuuint32_t*,
    CUtensorMapInterleave, CUtensorMapSwizzle, CUtensorMapL2promotion,
    CUtensorMapFloatOOBfill);

// Wfrag2: [ht_global 0..7][kc][wQ] 4KB blocks; inside: [nt][lane][reg] f16x2
__device__ __half Wfrag2[8 * NKC * 4 * 512];

// ---------------- helpers ----------------
__device__ __forceinline__ uint32_t smem_u32(const void* p) {
    uint32_t a;
    asm("{ .reg .u64 t; cvta.to.shared.u64 t, %1; cvt.u32.u64 %0, t; }" : "=r"(a) : "l"(p));
    return a;
}
__device__ __forceinline__ void mbar_init(uint32_t mbar, uint32_t cnt) {
    asm volatile("mbarrier.init.shared.b64 [%0], %1;" :: "r"(mbar), "r"(cnt) : "memory");
}
__device__ __forceinline__ void mbar_arrive(uint32_t mbar) {
    asm volatile("mbarrier.arrive.shared.b64 _, [%0];" :: "r"(mbar) : "memory");
}
__device__ __forceinline__ void mbar_expect_tx(uint32_t mbar, uint32_t bytes) {
    asm volatile("mbarrier.arrive.expect_tx.shared.b64 _, [%0], %1;"
                 :: "r"(mbar), "r"(bytes) : "memory");
}
__device__ __forceinline__ void mbar_wait(uint32_t mbar, uint32_t parity) {
    asm volatile(
        "{\n\t.reg .pred P;\n"
        "WL_%=:\n\t"
        "mbarrier.try_wait.parity.acquire.cta.shared::cta.b64 P, [%0], %1, 0x989680;\n\t"
        "@P bra.uni WD_%=;\n\t"
        "bra.uni WL_%=;\n"
        "WD_%=:\n\t}"
        :: "r"(mbar), "r"(parity) : "memory");
}
__device__ __forceinline__ void bulk_copy(uint32_t dst, const void* src,
                                          uint32_t bytes, uint32_t mbar) {
    asm volatile(
        "cp.async.bulk.shared::cta.global.mbarrier::complete_tx::bytes [%0], [%1], %2, [%3];"
        :: "r"(dst), "l"(src), "r"(bytes), "r"(mbar) : "memory");
}
__device__ __forceinline__ void tma_store2d(const CUtensorMap* tmap, int cx, int cy,
                                            uint32_t saddr) {
    asm volatile(
        "cp.async.bulk.tensor.2d.global.shared::cta.tile.bulk_group [%0, {%1, %2}], [%3];"
        :: "l"(tmap), "r"(cx), "r"(cy), "r"(saddr) : "memory");
}
__device__ __forceinline__ void tma_commit() {
    asm volatile("cp.async.bulk.commit_group;" ::: "memory");
}
__device__ __forceinline__ void tma_wait0() {
    asm volatile("cp.async.bulk.wait_group.read 0;" ::: "memory");
}
__device__ __forceinline__ void fence_async() {
    asm volatile("fence.proxy.async.shared::cta;" ::: "memory");
}

// A-fragment half index for element (row, k); one LDS.128 per (mt,kc,lane).
__device__ __forceinline__ int a_off(int row, int k) {
    int mt = row >> 4, half8 = (row >> 3) & 1, g = row & 7;
    int kc = k >> 4, khalf = (k >> 3) & 1, t = (k >> 1) & 3, kbit = k & 1;
    int lane = g * 4 + t;
    int reg = khalf * 2 + half8;
    return (((mt * NKC + kc) * 32 + lane) * 4 + reg) * 2 + kbit;
}

__device__ __forceinline__ void mma16(const uint32_t* a, const uint32_t* b, float* c) {
    asm volatile(
        "mma.sync.aligned.m16n8k16.row.col.f32.f16.f16.f32 "
        "{%0,%1,%2,%3}, {%4,%5,%6,%7}, {%8,%9}, {%0,%1,%2,%3};"
        : "+f"(c[0]), "+f"(c[1]), "+f"(c[2]), "+f"(c[3])
        : "r"(a[0]), "r"(a[1]), "r"(a[2]), "r"(a[3]), "r"(b[0]), "r"(b[1]));
}

__device__ __forceinline__ void sts4(uint32_t addr, float4 v) {
    asm volatile("st.shared.v4.f32 [%0], {%1,%2,%3,%4};"
                 :: "r"(addr), "f"(v.x), "f"(v.y), "f"(v.z), "f"(v.w) : "memory");
}

// ---------------- W -> B-fragment reorder ----------------
// h = htg*128 + wQ*32 + hl;  hl = t*8 + nt*2 + j  (t = C-frag lane&3)
__global__ void wfrag_kernel(const float* __restrict__ W) {
    int idx = blockIdx.x * blockDim.x + threadIdx.x;
    if (idx >= H_TOT * NKPAD) return;
    int h = idx / NKPAD;
    int k = idx - h * NKPAD;
    float v = (k < NK) ? W[h * NK + k] : 0.0f;
    int htg = h >> 7;
    int wQ = (h >> 5) & 3;
    int hl = h & 31;
    int t = hl >> 3;
    int rem = hl & 7;
    int nt = rem >> 1;
    int j = rem & 1;
    int n = t * 2 + j;
    int lane = n * 4 + ((k >> 1) & 3);
    int reg = (k >> 3) & 1;
    int kbit = k & 1;
    int kc = k >> 4;
    int block = (htg * NKC + kc) * 4 + wQ;
    Wfrag2[block * 512 + ((nt * 32 + lane) * 2 + reg) * 2 + kbit] = __float2half_rn(v);
}

// ---------------- main fused kernel ----------------
__global__ __launch_bounds__(NTHREADS, 2)
void sph_mma_kernel(const float* __restrict__ x,
                    const float* __restrict__ bvec,
                    const __grid_constant__ CUtensorMap tmap) {
    extern __shared__ __half smemh[];
    __half* Afrag = smemh;
    const uint32_t sbase = smem_u32(smemh);
    const uint32_t ring = sbase + RING_OFF;
    const uint32_t stg[2] = {sbase + STAGE_OFF, sbase + STAGE_OFF + 16384};
    const uint32_t full0 = sbase + MBAR_OFF;
    const uint32_t empty0 = sbase + MBAR_OFF + 64;

    const int tid = threadIdx.x;
    const int lane = tid & 31;
    const int wid = tid >> 5;
    const int wQ = wid & 3;          // N quarter (32 h within 128-h tile)
    const int wmt = (wid >> 2) * 4;  // M base in mtiles
    const int bid = blockIdx.x;
    const int pbase = (bid >> 1) * TILE_P;
    const int hhalf = bid & 1;       // which 512-h half
    const bool producer = (tid == 0);
    const char* gW = (const char*)Wfrag2 + (size_t)hhalf * NBLOCKS * 4096;

    if (tid == 0) {
        #pragma unroll
        for (int s = 0; s < STAGES; ++s) {
            mbar_init(full0 + s * 8, 1);
            mbar_init(empty0 + s * 8, 8);
        }
    }
    __syncthreads();

    if (producer) {
        #pragma unroll
        for (int g = 0; g < PROD_AHEAD; ++g) {
            mbar_expect_tx(full0 + g * 8, 4096);
            bulk_copy(ring + g * 4096, gW + (size_t)g * 4096, 4096, full0 + g * 8);
        }
    }

    // ---- generate Y for 128 pixels into A-fragment layout (threads 0..127) ----
    if (tid < TILE_P) {
        float2 tp = ((const float2*)x)[pbase + tid];
        const float theta = tp.x, phi = tp.y;
        const float ct = cosf(phi);
        const float st = sqrtf(fmaxf(1.0f - ct * ct, 0.0f));
        float pmm = 0.28209479177387814f;                 // sqrt(1/4pi)
        Afrag[a_off(tid, 64)] = __float2half_rn(1.7320508075688772f * ct * pmm);
        const float cth = cosf(theta), sth = sinf(theta);
        float cm = 1.0f, sm = 0.0f;
        #pragma unroll 1
        for (int m = 1; m <= 64; ++m) {
            pmm *= -sqrtf((2.0f * m + 1.0f) / (2.0f * m)) * st;
            float c2 = cm * cth - sm * sth;
            float s2 = sm * cth + cm * sth;
            cm = c2; sm = s2;
            float v = sqrtf(2.0f * m + 3.0f) * ct * pmm;
            v = (m & 1) ? (-1.41421356237309515f * v) : (1.41421356237309515f * v);
            Afrag[a_off(tid, 64 + m)] = __float2half_rn(v * cm);
            Afrag[a_off(tid, 64 - m)] = __float2half_rn(v * sm);
        }
        #pragma unroll
        for (int k = NK; k < NKPAD; ++k) Afrag[a_off(tid, k)] = __half(0.0f);
    }
    __syncthreads();

    const uint32_t abase = sbase;
    const uint32_t mystg = stg[wmt >> 2];   // warps 0-3 -> stage0, 4-7 -> stage1

    #pragma unroll 1
    for (int ht = 0; ht < NHT; ++ht) {
        float acc[4][4][4];
        #pragma unroll
        for (int mt = 0; mt < 4; ++mt)
            #pragma unroll
            for (int nt = 0; nt < 4; ++nt)
                #pragma unroll
                for (int i = 0; i < 4; ++i) acc[mt][nt][i] = 0.0f;

        #pragma unroll
        for (int kc = 0; kc < NKC; ++kc) {
            const int g = ht * NKC + kc;
            const int stage = g & (STAGES - 1);

            if (producer) {
                const int gp = g + PROD_AHEAD;
                if (gp < NBLOCKS) {
                    const int sp = gp & (STAGES - 1);
                    const int u = gp >> 3;
                    if (u >= 1) mbar_wait(empty0 + sp * 8, (u - 1) & 1);
                    mbar_expect_tx(full0 + sp * 8, 4096);
                    bulk_copy(ring + sp * 4096, gW + (size_t)gp * 4096,
                              4096, full0 + sp * 8);
                }
            }

            mbar_wait(full0 + stage * 8, (g >> 3) & 1);

            const uint32_t bs = ring + stage * 4096 + wQ * 1024 + lane * 8;
            uint32_t bfr[4][2];
            #pragma unroll
            for (int nt = 0; nt < 4; ++nt)
                asm volatile("ld.shared.v2.u32 {%0,%1}, [%2];"
                             : "=r"(bfr[nt][0]), "=r"(bfr[nt][1])
                             : "r"(bs + nt * 256));

            uint32_t afr[4][4];
            #pragma unroll
            for (int mt = 0; mt < 4; ++mt) {
                uint32_t addr = abase + ((((wmt + mt) * NKC + kc) * 32 + lane) * 4) * 4;
                asm volatile("ld.shared.v4.u32 {%0,%1,%2,%3}, [%4];"
                             : "=r"(afr[mt][0]), "=r"(afr[mt][1]),
                               "=r"(afr[mt][2]), "=r"(afr[mt][3])
                             : "r"(addr));
            }

            #pragma unroll
            for (int mt = 0; mt < 4; ++mt)
                #pragma unroll
                for (int nt = 0; nt < 4; ++nt)
                    mma16(afr[mt], bfr[nt], acc[mt][nt]);

            if (lane == 0) mbar_arrive(empty0 + stage * 8);
        }

        // ---- epilogue: stage (STS) + TMA 2D tensor store ----
        const int g8 = lane >> 2;
        const int t = lane & 3;
        const int hl = wQ * 32 + t * 8;                // h within 128-h tile
        const int hgl = hhalf * 512 + ht * 128 + hl;   // global h
        float4 bb0 = *(const float4*)&bvec[hgl];
        float4 bb1 = *(const float4*)&bvec[hgl + 4];

        #pragma unroll
        for (int round = 0; round < 2; ++round) {
            if (tid == 0) tma_wait0();    // stages free (prev round / prev ht)
            __syncthreads();
            #pragma unroll
            for (int m = 0; m < 2; ++m) {
                const int mt = round * 2 + m;
                const int lrow = m * 16 + g8;
                uint32_t a0 = mystg + lrow * 512 + hl * 4;
                float4 v0, v1;
                v0.x = acc[mt][0][0] + bb0.x;  v0.y = acc[mt][0][1] + bb0.y;
                v0.z = acc[mt][1][0] + bb0.z;  v0.w = acc[mt][1][1] + bb0.w;
                v1.x = acc[mt][2][0] + bb1.x;  v1.y = acc[mt][2][1] + bb1.y;
                v1.z = acc[mt][3][0] + bb1.z;  v1.w = acc[mt][3][1] + bb1.w;
                sts4(a0, v0);
                sts4(a0 + 16, v1);
                uint32_t a1 = a0 + 8 * 512;
                v0.x = acc[mt][0][2] + bb0.x;  v0.y = acc[mt][0][3] + bb0.y;
                v0.z = acc[mt][1][2] + bb0.z;  v0.w = acc[mt][1][3] + bb0.w;
                v1.x = acc[mt][2][2] + bb1.x;  v1.y = acc[mt][2][3] + bb1.y;
                v1.z = acc[mt][3][2] + bb1.z;  v1.w = acc[mt][3][3] + bb1.w;
                sts4(a1, v0);
                sts4(a1 + 16, v1);
            }
            fence_async();
            __syncthreads();
            if (tid == 0) {
                const int cx = hhalf * 512 + ht * 128;
                tma_store2d(&tmap, cx, pbase + round * 32, stg[0]);
                tma_store2d(&tmap, cx, pbase + 64 + round * 32, stg[1]);
                tma_commit();
            }
        }
    }
    if (tid == 0) tma_wait0();
    __syncthreads();
}

extern "C" void kernel_launch(void* const* d_in, const int* in_sizes, int n_in,
                              void* d_out, int out_size) {
    const float* x = (const float*)d_in[0];   // (P, 2)
    const float* W = (const float*)d_in[1];   // (1024, 129)
    const float* b = (const float*)d_in[2];   // (1024,)

    const int P = in_sizes[0] / 2;            // 131072

    // Build TMA descriptor for out[P][H] (f32, row-major).
    tmap_encode_fn fn = nullptr;
    cudaDriverEntryPointQueryResult qr;
    cudaGetDriverEntryPointByVersion("cuTensorMapEncodeTiled", (void**)&fn,
                                     12000, cudaEnableDefault, &qr);
    CUtensorMap tmap;
    {
        cuuint64_t dims[2] = {(cuuint64_t)H_TOT, (cuuint64_t)P};
        cuuint64_t strides[1] = {(cuuint64_t)H_TOT * 4};
        cuuint32_t box[2] = {128, 32};
        cuuint32_t estr[2] = {1, 1};
        fn(&tmap, CU_TENSOR_MAP_DATA_TYPE_FLOAT32, 2, d_out,
           dims, strides, box, estr,
           CU_TENSOR_MAP_INTERLEAVE_NONE, CU_TENSOR_MAP_SWIZZLE_NONE,
           CU_TENSOR_MAP_L2_PROMOTION_L2_128B, CU_TENSOR_MAP_FLOAT_OOB_FILL_NONE);
    }

    wfrag_kernel<<<(H_TOT * NKPAD + 255) / 256, 256>>>(W);

    cudaFuncSetAttribute(sph_mma_kernel,
                         cudaFuncAttributeMaxDynamicSharedMemorySize, SMEM_BYTES);
    sph_mma_kernel<<<(P / TILE_P) * 2, NTHREADS, SMEM_BYTES>>>(x, b, tmap);
}

// round 11
// speedup vs baseline: 1.0385x; 1.0385x over previous
#include <cuda_runtime.h>
#include <cuda_fp16.h>
#include <cstdint>
#include <math.h>

// SphericalFilter via mma.sync.m16n8k16 fp16 (fp32 accumulate).
// out[p,h] = sum_k Y[p,k] * W[h,k] + b[h];  P=131072, H=1024, K=129 (pad 144)
//
// R11 = R8 (best: free-running warps, cp.async.bulk B ring, streaming STG
// epilogue) + h-split grid: 2048 CTAs, each 128 pixels x 512 h, cutting the
// wave-quantization tail from 13.5% to ~1%. 256-thr CTAs, 64x32 warptile.

#define NK 129
#define NKPAD 144
#define NKC 9               // k-chunks of 16
#define H_TOT 1024
#define TILE_P 128
#define NTHREADS 256
#define NHT 4               // h-tiles (128h) per CTA -> 512 h
#define NBLOCKS (NHT * NKC) // 36 4KB B-blocks per CTA
#define STAGES 8
#define PROD_AHEAD 4

#define AFRAG_HALFS (8 * NKC * 32 * 8)          // 36864 B
#define RING_OFF (AFRAG_HALFS * 2)              // 36864
#define RING_BYTES (STAGES * 4096)              // 32768
#define MBAR_OFF (RING_OFF + RING_BYTES)        // 69632 (full[8] then empty[8])
#define SMEM_BYTES (MBAR_OFF + 128)             // 69760 B

// Wfrag2: [ht_global 0..7][kc][wQ] 4KB blocks; inside: [nt][lane][reg] f16x2
__device__ __half Wfrag2[8 * NKC * 4 * 512];

// ---------------- helpers ----------------
__device__ __forceinline__ uint32_t smem_u32(const void* p) {
    uint32_t a;
    asm("{ .reg .u64 t; cvta.to.shared.u64 t, %1; cvt.u32.u64 %0, t; }" : "=r"(a) : "l"(p));
    return a;
}
__device__ __forceinline__ void mbar_init(uint32_t mbar, uint32_t cnt) {
    asm volatile("mbarrier.init.shared.b64 [%0], %1;" :: "r"(mbar), "r"(cnt) : "memory");
}
__device__ __forceinline__ void mbar_arrive(uint32_t mbar) {
    asm volatile("mbarrier.arrive.shared.b64 _, [%0];" :: "r"(mbar) : "memory");
}
__device__ __forceinline__ void mbar_expect_tx(uint32_t mbar, uint32_t bytes) {
    asm volatile("mbarrier.arrive.expect_tx.shared.b64 _, [%0], %1;"
                 :: "r"(mbar), "r"(bytes) : "memory");
}
__device__ __forceinline__ void mbar_wait(uint32_t mbar, uint32_t parity) {
    asm volatile(
        "{\n\t.reg .pred P;\n"
        "WL_%=:\n\t"
        "mbarrier.try_wait.parity.acquire.cta.shared::cta.b64 P, [%0], %1, 0x989680;\n\t"
        "@P bra.uni WD_%=;\n\t"
        "bra.uni WL_%=;\n"
        "WD_%=:\n\t}"
        :: "r"(mbar), "r"(parity) : "memory");
}
__device__ __forceinline__ void bulk_copy(uint32_t dst, const void* src,
                                          uint32_t bytes, uint32_t mbar) {
    asm volatile(
        "cp.async.bulk.shared::cta.global.mbarrier::complete_tx::bytes [%0], [%1], %2, [%3];"
        :: "r"(dst), "l"(src), "r"(bytes), "r"(mbar) : "memory");
}

// A-fragment half index for element (row, k); one LDS.128 per (mt,kc,lane).
__device__ __forceinline__ int a_off(int row, int k) {
    int mt = row >> 4, half8 = (row >> 3) & 1, g = row & 7;
    int kc = k >> 4, khalf = (k >> 3) & 1, t = (k >> 1) & 3, kbit = k & 1;
    int lane = g * 4 + t;
    int reg = khalf * 2 + half8;
    return (((mt * NKC + kc) * 32 + lane) * 4 + reg) * 2 + kbit;
}

__device__ __forceinline__ void mma16(const uint32_t* a, const uint32_t* b, float* c) {
    asm volatile(
        "mma.sync.aligned.m16n8k16.row.col.f32.f16.f16.f32 "
        "{%0,%1,%2,%3}, {%4,%5,%6,%7}, {%8,%9}, {%0,%1,%2,%3};"
        : "+f"(c[0]), "+f"(c[1]), "+f"(c[2]), "+f"(c[3])
        : "r"(a[0]), "r"(a[1]), "r"(a[2]), "r"(a[3]), "r"(b[0]), "r"(b[1]));
}

__device__ __forceinline__ void stcs4(float* p, float4 v) {
    asm volatile("st.global.cs.v4.f32 [%0], {%1,%2,%3,%4};"
                 :: "l"(p), "f"(v.x), "f"(v.y), "f"(v.z), "f"(v.w) : "memory");
}

// ---------------- W -> B-fragment reorder ----------------
// h = htg*128 + wQ*32 + hl;  hl = t*8 + nt*2 + j  (t = C-frag lane&3)
__global__ void wfrag_kernel(const float* __restrict__ W) {
    int idx = blockIdx.x * blockDim.x + threadIdx.x;
    if (idx >= H_TOT * NKPAD) return;
    int h = idx / NKPAD;
    int k = idx - h * NKPAD;
    float v = (k < NK) ? W[h * NK + k] : 0.0f;
    int htg = h >> 7;
    int wQ = (h >> 5) & 3;
    int hl = h & 31;
    int t = hl >> 3;
    int rem = hl & 7;
    int nt = rem >> 1;
    int j = rem & 1;
    int n = t * 2 + j;
    int lane = n * 4 + ((k >> 1) & 3);
    int reg = (k >> 3) & 1;
    int kbit = k & 1;
    int kc = k >> 4;
    int block = (htg * NKC + kc) * 4 + wQ;
    Wfrag2[block * 512 + ((nt * 32 + lane) * 2 + reg) * 2 + kbit] = __float2half_rn(v);
}

// ---------------- main fused kernel ----------------
__global__ __launch_bounds__(NTHREADS, 2)
void sph_mma_kernel(const float* __restrict__ x,
                    const float* __restrict__ bvec,
                    float* __restrict__ out) {
    extern __shared__ __half smemh[];
    __half* Afrag = smemh;
    const uint32_t sbase = smem_u32(smemh);
    const uint32_t ring = sbase + RING_OFF;
    const uint32_t full0 = sbase + MBAR_OFF;
    const uint32_t empty0 = sbase + MBAR_OFF + 64;

    const int tid = threadIdx.x;
    const int lane = tid & 31;
    const int wid = tid >> 5;
    const int wQ = wid & 3;          // N quarter (32 h within a 128-h tile)
    const int wmt = (wid >> 2) * 4;  // M base in mtiles
    const int bid = blockIdx.x;
    const int pbase = (bid >> 1) * TILE_P;
    const int hhalf = bid & 1;       // which 512-h half this CTA covers
    const bool producer = (tid == 0);
    const char* gW = (const char*)Wfrag2 + (size_t)hhalf * NBLOCKS * 4096;

    if (tid == 0) {
        #pragma unroll
        for (int s = 0; s < STAGES; ++s) {
            mbar_init(full0 + s * 8, 1);    // expect_tx based
            mbar_init(empty0 + s * 8, 8);   // 8 consumer warps
        }
    }
    __syncthreads();

    if (producer) {
        #pragma unroll
        for (int g = 0; g < PROD_AHEAD; ++g) {
            mbar_expect_tx(full0 + g * 8, 4096);
            bulk_copy(ring + g * 4096, gW + (size_t)g * 4096, 4096, full0 + g * 8);
        }
    }

    // ---- generate Y for 128 pixels into A-fragment layout (threads 0..127) ----
    if (tid < TILE_P) {
        float2 tp = ((const float2*)x)[pbase + tid];
        const float theta = tp.x, phi = tp.y;
        const float ct = cosf(phi);
        const float st = sqrtf(fmaxf(1.0f - ct * ct, 0.0f));
        float pmm = 0.28209479177387814f;                 // sqrt(1/4pi)
        Afrag[a_off(tid, 64)] = __float2half_rn(1.7320508075688772f * ct * pmm);
        const float cth = cosf(theta), sth = sinf(theta);
        float cm = 1.0f, sm = 0.0f;
        #pragma unroll 1
        for (int m = 1; m <= 64; ++m) {
            pmm *= -sqrtf((2.0f * m + 1.0f) / (2.0f * m)) * st;
            float c2 = cm * cth - sm * sth;
            float s2 = sm * cth + cm * sth;
            cm = c2; sm = s2;
            float v = sqrtf(2.0f * m + 3.0f) * ct * pmm;
            v = (m & 1) ? (-1.41421356237309515f * v) : (1.41421356237309515f * v);
            Afrag[a_off(tid, 64 + m)] = __float2half_rn(v * cm);
            Afrag[a_off(tid, 64 - m)] = __float2half_rn(v * sm);
        }
        #pragma unroll
        for (int k = NK; k < NKPAD; ++k) Afrag[a_off(tid, k)] = __half(0.0f);
    }
    __syncthreads();

    const uint32_t abase = sbase;   // Afrag at smem offset 0

    #pragma unroll 1
    for (int ht = 0; ht < NHT; ++ht) {
        float acc[4][4][4];
        #pragma unroll
        for (int mt = 0; mt < 4; ++mt)
            #pragma unroll
            for (int nt = 0; nt < 4; ++nt)
                #pragma unroll
                for (int i = 0; i < 4; ++i) acc[mt][nt][i] = 0.0f;

        #pragma unroll
        for (int kc = 0; kc < NKC; ++kc) {
            const int g = ht * NKC + kc;       // block index within CTA stream
            const int stage = g & (STAGES - 1);

            // producer: issue block g+PROD_AHEAD into its stage
            if (producer) {
                const int gp = g + PROD_AHEAD;
                if (gp < NBLOCKS) {
                    const int sp = gp & (STAGES - 1);
                    const int u = gp >> 3;     // usage index of stage sp
                    if (u >= 1) mbar_wait(empty0 + sp * 8, (u - 1) & 1);
                    mbar_expect_tx(full0 + sp * 8, 4096);
                    bulk_copy(ring + sp * 4096, gW + (size_t)gp * 4096,
                              4096, full0 + sp * 8);
                }
            }

            // consumer: wait for block g
            mbar_wait(full0 + stage * 8, (g >> 3) & 1);

            // B fragments for this warp's wQ slice
            const uint32_t bs = ring + stage * 4096 + wQ * 1024 + lane * 8;
            uint32_t bfr[4][2];
            #pragma unroll
            for (int nt = 0; nt < 4; ++nt)
                asm volatile("ld.shared.v2.u32 {%0,%1}, [%2];"
                             : "=r"(bfr[nt][0]), "=r"(bfr[nt][1])
                             : "r"(bs + nt * 256));

            // A fragments for this kc
            uint32_t afr[4][4];
            #pragma unroll
            for (int mt = 0; mt < 4; ++mt) {
                uint32_t addr = abase + ((((wmt + mt) * NKC + kc) * 32 + lane) * 4) * 4;
                asm volatile("ld.shared.v4.u32 {%0,%1,%2,%3}, [%4];"
                             : "=r"(afr[mt][0]), "=r"(afr[mt][1]),
                               "=r"(afr[mt][2]), "=r"(afr[mt][3])
                             : "r"(addr));
            }

            #pragma unroll
            for (int mt = 0; mt < 4; ++mt)
                #pragma unroll
                for (int nt = 0; nt < 4; ++nt)
                    mma16(afr[mt], bfr[nt], acc[mt][nt]);

            if (lane == 0) mbar_arrive(empty0 + stage * 8);
        }

        // ---- epilogue: 8 consecutive h per lane -> 2x streaming STG.128/row ----
        const int g8 = lane >> 2;
        const int hb = hhalf * 512 + ht * 128 + wQ * 32 + (lane & 3) * 8;
        float4 bb0 = *(const float4*)&bvec[hb];
        float4 bb1 = *(const float4*)&bvec[hb + 4];
        #pragma unroll
        for (int mt = 0; mt < 4; ++mt) {
            const int p0 = pbase + (wmt + mt) * 16 + g8;
            float* o0 = &out[(size_t)p0 * H_TOT + hb];
            float* o1 = &out[(size_t)(p0 + 8) * H_TOT + hb];
            float4 v0, v1;
            // row g8
            v0.x = acc[mt][0][0] + bb0.x;  v0.y = acc[mt][0][1] + bb0.y;
            v0.z = acc[mt][1][0] + bb0.z;  v0.w = acc[mt][1][1] + bb0.w;
            v1.x = acc[mt][2][0] + bb1.x;  v1.y = acc[mt][2][1] + bb1.y;
            v1.z = acc[mt][3][0] + bb1.z;  v1.w = acc[mt][3][1] + bb1.w;
            stcs4(o0 + 0, v0);
            stcs4(o0 + 4, v1);
            // row g8+8
            v0.x = acc[mt][0][2] + bb0.x;  v0.y = acc[mt][0][3] + bb0.y;
            v0.z = acc[mt][1][2] + bb0.z;  v0.w = acc[mt][1][3] + bb0.w;
            v1.x = acc[mt][2][2] + bb1.x;  v1.y = acc[mt][2][3] + bb1.y;
            v1.z = acc[mt][3][2] + bb1.z;  v1.w = acc[mt][3][3] + bb1.w;
            stcs4(o1 + 0, v0);
            stcs4(o1 + 4, v1);
        }
    }
}

extern "C" void kernel_launch(void* const* d_in, const int* in_sizes, int n_in,
                              void* d_out, int out_size) {
    const float* x = (const float*)d_in[0];   // (P, 2)
    const float* W = (const float*)d_in[1];   // (1024, 129)
    const float* b = (const float*)d_in[2];   // (1024,)
    float* out = (float*)d_out;               // (P, 1024)

    const int P = in_sizes[0] / 2;            // 131072

    wfrag_kernel<<<(H_TOT * NKPAD + 255) / 256, 256>>>(W);

    cudaFuncSetAttribute(sph_mma_kernel,
                         cudaFuncAttributeMaxDynamicSharedMemorySize, SMEM_BYTES);
    sph_mma_kernel<<<(P / TILE_P) * 2, NTHREADS, SMEM_BYTES>>>(x, b, out);
}

// round 12
// speedup vs baseline: 1.3635x; 1.3130x over previous
#include <cuda_runtime.h>
#include <cuda_fp16.h>
#include <cstdint>
#include <math.h>

// SphericalFilter via mma.sync.m16n8k16 fp16 (fp32 accumulate).
// out[p,h] = sum_k Y[p,k] * W[h,k] + b[h];  P=131072, H=1024, K=129 (pad 144)
//
// R12 = R8 (1024 CTAs, free-running warps, cp.async.bulk B ring, streaming
// STG epilogue) with: (a) 12KB ring blocks (3 kc each, aligned to ht tiles)
// -> mbarrier waits per warp 72 -> 24; (b) Y-recurrence constants tabulated
// by the prep kernel -> shorter serial chain, no MUFU sqrt in the loop.

#define NK 129
#define NKPAD 144
#define NKC 9               // k-chunks of 16 per ht
#define KCB 3               // kc per ring block
#define H_TOT 1024
#define TILE_P 128
#define NTHREADS 256
#define NTILES_H 8
#define NBLK (NTILES_H * NKC / KCB)   // 24 12KB blocks per CTA
#define STAGES 4
#define PROD_AHEAD 2
#define BLK_BYTES (KCB * 4096)        // 12288

#define AFRAG_HALFS (8 * NKC * 32 * 8)          // 36864 B
#define RING_OFF (AFRAG_HALFS * 2)              // 36864
#define RING_BYTES (STAGES * BLK_BYTES)         // 49152
#define MBAR_OFF (RING_OFF + RING_BYTES)        // 86016 (full[4] then empty[4])
#define SMEM_BYTES (MBAR_OFF + 128)             // 86144 B

// Wfrag2: [ht 0..7][kc 0..8][wQ] 4KB units; inside: [nt][lane][reg] f16x2
__device__ __half Wfrag2[8 * NKC * 4 * 512];
// Y recurrence constants: x = -sqrt((2m+1)/(2m)), y = (+-sqrt2)*sqrt(2m+3)
__device__ float2 Ycst[65];

// ---------------- helpers ----------------
__device__ __forceinline__ uint32_t smem_u32(const void* p) {
    uint32_t a;
    asm("{ .reg .u64 t; cvta.to.shared.u64 t, %1; cvt.u32.u64 %0, t; }" : "=r"(a) : "l"(p));
    return a;
}
__device__ __forceinline__ void mbar_init(uint32_t mbar, uint32_t cnt) {
    asm volatile("mbarrier.init.shared.b64 [%0], %1;" :: "r"(mbar), "r"(cnt) : "memory");
}
__device__ __forceinline__ void mbar_arrive(uint32_t mbar) {
    asm volatile("mbarrier.arrive.shared.b64 _, [%0];" :: "r"(mbar) : "memory");
}
__device__ __forceinline__ void mbar_expect_tx(uint32_t mbar, uint32_t bytes) {
    asm volatile("mbarrier.arrive.expect_tx.shared.b64 _, [%0], %1;"
                 :: "r"(mbar), "r"(bytes) : "memory");
}
__device__ __forceinline__ void mbar_wait(uint32_t mbar, uint32_t parity) {
    asm volatile(
        "{\n\t.reg .pred P;\n"
        "WL_%=:\n\t"
        "mbarrier.try_wait.parity.acquire.cta.shared::cta.b64 P, [%0], %1, 0x989680;\n\t"
        "@P bra.uni WD_%=;\n\t"
        "bra.uni WL_%=;\n"
        "WD_%=:\n\t}"
        :: "r"(mbar), "r"(parity) : "memory");
}
__device__ __forceinline__ void bulk_copy(uint32_t dst, const void* src,
                                          uint32_t bytes, uint32_t mbar) {
    asm volatile(
        "cp.async.bulk.shared::cta.global.mbarrier::complete_tx::bytes [%0], [%1], %2, [%3];"
        :: "r"(dst), "l"(src), "r"(bytes), "r"(mbar) : "memory");
}

// A-fragment half index for element (row, k); one LDS.128 per (mt,kc,lane).
__device__ __forceinline__ int a_off(int row, int k) {
    int mt = row >> 4, half8 = (row >> 3) & 1, g = row & 7;
    int kc = k >> 4, khalf = (k >> 3) & 1, t = (k >> 1) & 3, kbit = k & 1;
    int lane = g * 4 + t;
    int reg = khalf * 2 + half8;
    return (((mt * NKC + kc) * 32 + lane) * 4 + reg) * 2 + kbit;
}

__device__ __forceinline__ void mma16(const uint32_t* a, const uint32_t* b, float* c) {
    asm volatile(
        "mma.sync.aligned.m16n8k16.row.col.f32.f16.f16.f32 "
        "{%0,%1,%2,%3}, {%4,%5,%6,%7}, {%8,%9}, {%0,%1,%2,%3};"
        : "+f"(c[0]), "+f"(c[1]), "+f"(c[2]), "+f"(c[3])
        : "r"(a[0]), "r"(a[1]), "r"(a[2]), "r"(a[3]), "r"(b[0]), "r"(b[1]));
}

__device__ __forceinline__ void stcs4(float* p, float4 v) {
    asm volatile("st.global.cs.v4.f32 [%0], {%1,%2,%3,%4};"
                 :: "l"(p), "f"(v.x), "f"(v.y), "f"(v.z), "f"(v.w) : "memory");
}

// ---------------- W -> B-fragment reorder + Y constant table ----------------
// h = htg*128 + wQ*32 + hl;  hl = t*8 + nt*2 + j  (t = C-frag lane&3)
__global__ void wfrag_kernel(const float* __restrict__ W) {
    int idx = blockIdx.x * blockDim.x + threadIdx.x;
    if (blockIdx.x == 0 && threadIdx.x >= 1 && threadIdx.x <= 64) {
        int m = threadIdx.x;
        float2 c;
        c.x = -sqrtf((2.0f * m + 1.0f) / (2.0f * m));
        c.y = ((m & 1) ? -1.41421356237309515f : 1.41421356237309515f)
              * sqrtf(2.0f * m + 3.0f);
        Ycst[m] = c;
    }
    if (idx >= H_TOT * NKPAD) return;
    int h = idx / NKPAD;
    int k = idx - h * NKPAD;
    float v = (k < NK) ? W[h * NK + k] : 0.0f;
    int htg = h >> 7;
    int wQ = (h >> 5) & 3;
    int hl = h & 31;
    int t = hl >> 3;
    int rem = hl & 7;
    int nt = rem >> 1;
    int j = rem & 1;
    int n = t * 2 + j;
    int lane = n * 4 + ((k >> 1) & 3);
    int reg = (k >> 3) & 1;
    int kbit = k & 1;
    int kc = k >> 4;
    int block = (htg * NKC + kc) * 4 + wQ;
    Wfrag2[block * 512 + ((nt * 32 + lane) * 2 + reg) * 2 + kbit] = __float2half_rn(v);
}

// ---------------- main fused kernel ----------------
__global__ __launch_bounds__(NTHREADS, 2)
void sph_mma_kernel(const float* __restrict__ x,
                    const float* __restrict__ bvec,
                    float* __restrict__ out) {
    extern __shared__ __half smemh[];
    __half* Afrag = smemh;
    const uint32_t sbase = smem_u32(smemh);
    const uint32_t ring = sbase + RING_OFF;
    const uint32_t full0 = sbase + MBAR_OFF;
    const uint32_t empty0 = sbase + MBAR_OFF + 64;

    const int tid = threadIdx.x;
    const int lane = tid & 31;
    const int wid = tid >> 5;
    const int wQ = wid & 3;          // N quarter (32 h within a 128-h tile)
    const int wmt = (wid >> 2) * 4;  // M base in mtiles
    const int pbase = blockIdx.x * TILE_P;
    const bool producer = (tid == 0);
    const char* gW = (const char*)Wfrag2;

    if (tid == 0) {
        #pragma unroll
        for (int s = 0; s < STAGES; ++s) {
            mbar_init(full0 + s * 8, 1);    // expect_tx based
            mbar_init(empty0 + s * 8, 8);   // 8 consumer warps
        }
    }
    __syncthreads();

    if (producer) {
        #pragma unroll
        for (int b = 0; b < PROD_AHEAD; ++b) {
            mbar_expect_tx(full0 + b * 8, BLK_BYTES);
            bulk_copy(ring + b * BLK_BYTES, gW + (size_t)b * BLK_BYTES,
                      BLK_BYTES, full0 + b * 8);
        }
    }

    // ---- generate Y for 128 pixels into A-fragment layout (threads 0..127) ----
    if (tid < TILE_P) {
        float2 tp = ((const float2*)x)[pbase + tid];
        const float theta = tp.x, phi = tp.y;
        const float ct = cosf(phi);
        const float st = sqrtf(fmaxf(1.0f - ct * ct, 0.0f));
        float pmm = 0.28209479177387814f;                 // sqrt(1/4pi)
        Afrag[a_off(tid, 64)] = __float2half_rn(1.7320508075688772f * ct * pmm);
        const float cth = cosf(theta), sth = sinf(theta);
        float cm = 1.0f, sm = 0.0f;
        const float2* __restrict__ yc = Ycst;
        #pragma unroll 4
        for (int m = 1; m <= 64; ++m) {
            float2 c = __ldg(&yc[m]);
            pmm *= c.x * st;                               // 1-mul chain
            float c2 = cm * cth - sm * sth;
            float s2 = sm * cth + cm * sth;
            cm = c2; sm = s2;
            float v = c.y * ct * pmm;
            Afrag[a_off(tid, 64 + m)] = __float2half_rn(v * cm);
            Afrag[a_off(tid, 64 - m)] = __float2half_rn(v * sm);
        }
        #pragma unroll
        for (int k = NK; k < NKPAD; ++k) Afrag[a_off(tid, k)] = __half(0.0f);
    }
    __syncthreads();

    const uint32_t abase = sbase;   // Afrag at smem offset 0

    #pragma unroll 1
    for (int ht = 0; ht < NTILES_H; ++ht) {
        float acc[4][4][4];
        #pragma unroll
        for (int mt = 0; mt < 4; ++mt)
            #pragma unroll
            for (int nt = 0; nt < 4; ++nt)
                #pragma unroll
                for (int i = 0; i < 4; ++i) acc[mt][nt][i] = 0.0f;

        #pragma unroll
        for (int kcb = 0; kcb < NKC / KCB; ++kcb) {
            const int b = ht * (NKC / KCB) + kcb;   // ring block index
            const int stage = b & (STAGES - 1);

            // producer: issue block b+PROD_AHEAD
            if (producer) {
                const int bp = b + PROD_AHEAD;
                if (bp < NBLK) {
                    const int sp = bp & (STAGES - 1);
                    const int u = bp >> 2;          // usage index of stage sp
                    if (u >= 1) mbar_wait(empty0 + sp * 8, (u - 1) & 1);
                    mbar_expect_tx(full0 + sp * 8, BLK_BYTES);
                    bulk_copy(ring + sp * BLK_BYTES, gW + (size_t)bp * BLK_BYTES,
                              BLK_BYTES, full0 + sp * 8);
                }
            }

            // consumer: one wait per 3 kc
            mbar_wait(full0 + stage * 8, (b >> 2) & 1);

            #pragma unroll
            for (int kci = 0; kci < KCB; ++kci) {
                const int kc = kcb * KCB + kci;

                const uint32_t bs = ring + stage * BLK_BYTES + kci * 4096
                                  + wQ * 1024 + lane * 8;
                uint32_t bfr[4][2];
                #pragma unroll
                for (int nt = 0; nt < 4; ++nt)
                    asm volatile("ld.shared.v2.u32 {%0,%1}, [%2];"
                                 : "=r"(bfr[nt][0]), "=r"(bfr[nt][1])
                                 : "r"(bs + nt * 256));

                uint32_t afr[4][4];
                #pragma unroll
                for (int mt = 0; mt < 4; ++mt) {
                    uint32_t addr = abase + ((((wmt + mt) * NKC + kc) * 32 + lane) * 4) * 4;
                    asm volatile("ld.shared.v4.u32 {%0,%1,%2,%3}, [%4];"
                                 : "=r"(afr[mt][0]), "=r"(afr[mt][1]),
                                   "=r"(afr[mt][2]), "=r"(afr[mt][3])
                                 : "r"(addr));
                }

                #pragma unroll
                for (int mt = 0; mt < 4; ++mt)
                    #pragma unroll
                    for (int nt = 0; nt < 4; ++nt)
                        mma16(afr[mt], bfr[nt], acc[mt][nt]);
            }

            if (lane == 0) mbar_arrive(empty0 + stage * 8);
        }

        // ---- epilogue: 8 consecutive h per lane -> 2x streaming STG.128/row ----
        const int g8 = lane >> 2;
        const int hb = ht * 128 + wQ * 32 + (lane & 3) * 8;
        float4 bb0 = *(const float4*)&bvec[hb];
        float4 bb1 = *(const float4*)&bvec[hb + 4];
        #pragma unroll
        for (int mt = 0; mt < 4; ++mt) {
            const int p0 = pbase + (wmt + mt) * 16 + g8;
            float* o0 = &out[(size_t)p0 * H_TOT + hb];
            float* o1 = &out[(size_t)(p0 + 8) * H_TOT + hb];
            float4 v0, v1;
            // row g8
            v0.x = acc[mt][0][0] + bb0.x;  v0.y = acc[mt][0][1] + bb0.y;
            v0.z = acc[mt][1][0] + bb0.z;  v0.w = acc[mt][1][1] + bb0.w;
            v1.x = acc[mt][2][0] + bb1.x;  v1.y = acc[mt][2][1] + bb1.y;
            v1.z = acc[mt][3][0] + bb1.z;  v1.w = acc[mt][3][1] + bb1.w;
            stcs4(o0 + 0, v0);
            stcs4(o0 + 4, v1);
            // row g8+8
            v0.x = acc[mt][0][2] + bb0.x;  v0.y = acc[mt][0][3] + bb0.y;
            v0.z = acc[mt][1][2] + bb0.z;  v0.w = acc[mt][1][3] + bb0.w;
            v1.x = acc[mt][2][2] + bb1.x;  v1.y = acc[mt][2][3] + bb1.y;
            v1.z = acc[mt][3][2] + bb1.z;  v1.w = acc[mt][3][3] + bb1.w;
            stcs4(o1 + 0, v0);
            stcs4(o1 + 4, v1);
        }
    }
}

extern "C" void kernel_launch(void* const* d_in, const int* in_sizes, int n_in,
                              void* d_out, int out_size) {
    const float* x = (const float*)d_in[0];   // (P, 2)
    const float* W = (const float*)d_in[1];   // (1024, 129)
    const float* b = (const float*)d_in[2];   // (1024,)
    float* out = (float*)d_out;               // (P, 1024)

    const int P = in_sizes[0] / 2;            // 131072

    wfrag_kernel<<<(H_TOT * NKPAD + 255) / 256, 256>>>(W);

    cudaFuncSetAttribute(sph_mma_kernel,
                         cudaFuncAttributeMaxDynamicSharedMemorySize, SMEM_BYTES);
    sph_mma_kernel<<<P / TILE_P, NTHREADS, SMEM_BYTES>>>(x, b, out);
}